// round 7
// baseline (speedup 1.0000x reference)
#include <cuda_runtime.h>
#include <cstdint>

#define BTc 16
#define Nc 1024
#define Dc 128
#define Hc 8
#define HDc 16
#define Mc (BTc*Nc)   // 16384 rows

// ---- scratch (no allocations allowed) ----
__device__ float g_q[(size_t)BTc*Hc*Nc*HDc];   // 8 MB, head-major, pre-scaled by log2e/4
__device__ float g_k[(size_t)BTc*Hc*Nc*HDc];   // 8 MB
__device__ float g_v[(size_t)BTc*Hc*Nc*HDc];   // 8 MB
__device__ float g_ctx[(size_t)Mc*Dc];         // 8 MB

// ---- packed f32x2 helpers (FFMA2 is PTX-only on sm_103a) ----
typedef unsigned long long f2_t;

__device__ __forceinline__ f2_t f2_mul(f2_t a, f2_t b){ f2_t r; asm("mul.rn.f32x2 %0,%1,%2;":"=l"(r):"l"(a),"l"(b)); return r; }
__device__ __forceinline__ f2_t f2_fma(f2_t a, f2_t b, f2_t c){ f2_t r; asm("fma.rn.f32x2 %0,%1,%2,%3;":"=l"(r):"l"(a),"l"(b),"l"(c)); return r; }
__device__ __forceinline__ f2_t f2_add(f2_t a, f2_t b){ f2_t r; asm("add.rn.f32x2 %0,%1,%2;":"=l"(r):"l"(a),"l"(b)); return r; }
__device__ __forceinline__ f2_t f2_pack(float lo, float hi){ f2_t r; asm("mov.b64 %0,{%1,%2};":"=l"(r):"f"(lo),"f"(hi)); return r; }
__device__ __forceinline__ void f2_unpack(f2_t a, float& lo, float& hi){ asm("mov.b64 {%0,%1},%2;":"=f"(lo),"=f"(hi):"l"(a)); }
__device__ __forceinline__ float fast_ex2(float x){ float r; asm("ex2.approx.f32 %0,%1;":"=f"(r):"f"(x)); return r; }

// ============================================================
// GEMM tile: 128 rows x 128 cols, K=128.  out = X @ W^T  (torch Linear)
// ============================================================
__device__ __forceinline__ void gemm_tile(const float* __restrict__ Xg,
                                          const float* __restrict__ Wg,
                                          float* Xs, float* Ws,
                                          f2_t acc2[8][4], int m0, int tid)
{
    #pragma unroll
    for (int it = 0; it < 16; ++it) {
        int idx = it*256 + tid;
        int m = idx >> 5, k4 = idx & 31;
        *(float4*)(Xs + m*132 + k4*4) = *(const float4*)(Xg + (size_t)(m0+m)*128 + k4*4);
        *(float4*)(Ws + m*132 + k4*4) = *(const float4*)(Wg + (size_t)m*128 + k4*4);
    }
    __syncthreads();

    int tx = tid & 15, ty = tid >> 4;
    #pragma unroll
    for (int i = 0; i < 8; ++i)
        #pragma unroll
        for (int t = 0; t < 4; ++t) acc2[i][t] = 0ULL;

    #pragma unroll 4
    for (int k = 0; k < 128; ++k) {
        f2_t a2[8], b2[4];
        #pragma unroll
        for (int i = 0; i < 8; ++i) {
            float a = Xs[(ty*8+i)*132 + k];
            a2[i] = f2_pack(a, a);
        }
        #pragma unroll
        for (int t = 0; t < 4; ++t) {
            float blo = Ws[(tx + 32*t)*132 + k];
            float bhi = Ws[(tx + 32*t + 16)*132 + k];
            b2[t] = f2_pack(blo, bhi);
        }
        #pragma unroll
        for (int i = 0; i < 8; ++i)
            #pragma unroll
            for (int t = 0; t < 4; ++t)
                acc2[i][t] = f2_fma(a2[i], b2[t], acc2[i][t]);
    }
}

// ============================================================
// QKV projection: grid (128, 3), 256 thr.  Writes head-major (bt,h,n,hd).
// ============================================================
__global__ void __launch_bounds__(256) proj_qkv_kernel(
    const float* __restrict__ x,
    const float* __restrict__ Wq, const float* __restrict__ bq,
    const float* __restrict__ Wk, const float* __restrict__ bk,
    const float* __restrict__ Wv, const float* __restrict__ bv)
{
    extern __shared__ float sm[];
    float* Xs = sm;
    float* Ws = sm + 128*132;

    int sel = blockIdx.y;
    const float* W    = (sel == 0) ? Wq : (sel == 1) ? Wk : Wv;
    const float* bias = (sel == 0) ? bq : (sel == 1) ? bk : bv;
    float*       out  = (sel == 0) ? g_q : (sel == 1) ? g_k : g_v;
    float scale = (sel == 0) ? (0.25f * 1.4426950408889634f) : 1.0f;

    int m0 = blockIdx.x * 128;
    f2_t acc2[8][4];
    gemm_tile(x, W, Xs, Ws, acc2, m0, threadIdx.x);

    int tx = threadIdx.x & 15, ty = threadIdx.x >> 4;
    int bt = m0 / Nc;
    int nbase = m0 % Nc;
    #pragma unroll
    for (int i = 0; i < 8; ++i) {
        int n = nbase + ty*8 + i;
        #pragma unroll
        for (int t = 0; t < 4; ++t) {
            float lo, hi; f2_unpack(acc2[i][t], lo, hi);
            int j0 = tx + 32*t, j1 = j0 + 16;
            float v0 = (lo + bias[j0]) * scale;
            float v1 = (hi + bias[j1]) * scale;
            out[(((size_t)bt*Hc + (j0 >> 4))*Nc + n)*HDc + (j0 & 15)] = v0;
            out[(((size_t)bt*Hc + (j1 >> 4))*Nc + n)*HDc + (j1 & 15)] = v1;
        }
    }
}

// ============================================================
// O projection
// ============================================================
__global__ void __launch_bounds__(256) proj_o_kernel(
    const float* __restrict__ Wo, const float* __restrict__ bo,
    float* __restrict__ out)
{
    extern __shared__ float sm[];
    float* Xs = sm;
    float* Ws = sm + 128*132;

    int m0 = blockIdx.x * 128;
    f2_t acc2[8][4];
    gemm_tile(g_ctx, Wo, Xs, Ws, acc2, m0, threadIdx.x);

    int tx = threadIdx.x & 15, ty = threadIdx.x >> 4;
    #pragma unroll
    for (int i = 0; i < 8; ++i) {
        size_t m = m0 + ty*8 + i;
        #pragma unroll
        for (int t = 0; t < 4; ++t) {
            float lo, hi; f2_unpack(acc2[i][t], lo, hi);
            int j0 = tx + 32*t, j1 = j0 + 16;
            out[m*Dc + j0] = lo + bo[j0];
            out[m*Dc + j1] = hi + bo[j1];
        }
    }
}

// ============================================================
// Fused attention v4: one CTA = one (bt, h) slab, 512 thr, R=2 rows/thr.
// 4 warps/SMSP (vs 2) for latency hiding; same fma-issue floor.
// adj double-buffered smem staging, 1 barrier/chunk.
// ============================================================
#define CHUNK 8
#define NCHUNK (Nc/CHUNK)         // 128
#define APAD 1028                 // %32==4 (conflict-free transpose STS)

__global__ void __launch_bounds__(512,1) attn_kernel(const float* __restrict__ adj)
{
    extern __shared__ float sm[];
    float* Ks = sm;                       // [1024][16]
    float* Vs = sm + Nc*HDc;              // [1024][16]
    float* Abuf = sm + 2*Nc*HDc;          // 2 x [CHUNK][APAD]

    int bt = blockIdx.x >> 3;
    int h  = blockIdx.x & 7;
    int slab = bt*Hc + h;
    int t = threadIdx.x;

    // ---- load K,V slab (coalesced) ----
    const float* kg = g_k + (size_t)slab*Nc*HDc;
    const float* vg = g_v + (size_t)slab*Nc*HDc;
    #pragma unroll
    for (int i = t; i < Nc*HDc/4; i += 512) {
        ((float4*)Ks)[i] = ((const float4*)kg)[i];
        ((float4*)Vs)[i] = ((const float4*)vg)[i];
    }

    // ---- load q for my 2 rows (pre-scaled by log2e/4) ----
    int r0 = 2*t;
    f2_t q2[2][8];
    const float* qp = g_q + ((size_t)slab*Nc + r0)*HDc;
    #pragma unroll
    for (int rr = 0; rr < 2; ++rr)
        #pragma unroll
        for (int j = 0; j < 4; ++j) {
            float4 f = *(const float4*)(qp + rr*HDc + j*4);
            q2[rr][2*j]   = f2_pack(f.x, f.y);
            q2[rr][2*j+1] = f2_pack(f.z, f.w);
        }

    f2_t acc2[2][8];
    #pragma unroll
    for (int rr = 0; rr < 2; ++rr)
        #pragma unroll
        for (int j = 0; j < 8; ++j) acc2[rr][j] = 0ULL;
    float sum[2] = {0.f, 0.f};

    // adj: chunk tile = [1024 rows][8 cols] = 2048 float4s, 4 per thread.
    // element e = it*512 + t  ->  row = e>>1, colgroup cq = e&1 (4 cols each)
    const float* ag = adj + (size_t)bt*Nc*Nc;
    float4 pf[4];
    #pragma unroll
    for (int it = 0; it < 4; ++it) {
        int e = it*512 + t;
        int r = e >> 1, cq = e & 1;
        pf[it] = *(const float4*)(ag + (size_t)r*Nc + 4*cq);
    }
    __syncthreads();   // K,V ready

    for (int chunk = 0; chunk < NCHUNK; ++chunk) {
        float* As = Abuf + (chunk & 1) * (CHUNK*APAD);

        // ---- store prefetched chunk transposed (conflict-free) ----
        #pragma unroll
        for (int it = 0; it < 4; ++it) {
            int e = it*512 + t;
            int r = e >> 1, cq = e & 1;
            As[(4*cq+0)*APAD + r] = pf[it].x;
            As[(4*cq+1)*APAD + r] = pf[it].y;
            As[(4*cq+2)*APAD + r] = pf[it].z;
            As[(4*cq+3)*APAD + r] = pf[it].w;
        }
        // ---- prefetch next chunk ----
        int nchunk = (chunk+1 < NCHUNK) ? (chunk+1) : 0;
        const float* agn = ag + nchunk*CHUNK;
        #pragma unroll
        for (int it = 0; it < 4; ++it) {
            int e = it*512 + t;
            int r = e >> 1, cq = e & 1;
            pf[it] = *(const float4*)(agn + (size_t)r*Nc + 4*cq);
        }
        __syncthreads();   // As writes visible; prior buffer reads complete

        int c0 = chunk*CHUNK;
        #pragma unroll 2
        for (int lc = 0; lc < CHUNK; ++lc) {
            int c = c0 + lc;
            const ulonglong2* kr = (const ulonglong2*)(Ks + c*HDc);
            ulonglong2 k0 = kr[0], k1 = kr[1], k2 = kr[2], k3 = kr[3];
            const ulonglong2* vr = (const ulonglong2*)(Vs + c*HDc);
            ulonglong2 v0 = vr[0], v1 = vr[1], v2 = vr[2], v3 = vr[3];
            // adj for my 2 rows at column c: one LDS.64
            float2 a2v = *(const float2*)(As + lc*APAD + r0);
            float aarr[2] = {a2v.x, a2v.y};

            #pragma unroll
            for (int rr = 0; rr < 2; ++rr) {
                // 9-op dot: two parallel chains
                f2_t d0 = f2_mul(q2[rr][0], k0.x);
                f2_t d1 = f2_mul(q2[rr][1], k0.y);
                d0 = f2_fma(q2[rr][2], k1.x, d0);
                d1 = f2_fma(q2[rr][3], k1.y, d1);
                d0 = f2_fma(q2[rr][4], k2.x, d0);
                d1 = f2_fma(q2[rr][5], k2.y, d1);
                d0 = f2_fma(q2[rr][6], k3.x, d0);
                d1 = f2_fma(q2[rr][7], k3.y, d1);
                d0 = f2_add(d0, d1);
                float lo, hi; f2_unpack(d0, lo, hi);
                float s = lo + hi;                 // log2-domain score

                float p = fast_ex2(s) * aarr[rr];  // MUFU pipe
                sum[rr] += p;
                f2_t pp = f2_pack(p, p);

                acc2[rr][0] = f2_fma(pp, v0.x, acc2[rr][0]);
                acc2[rr][1] = f2_fma(pp, v0.y, acc2[rr][1]);
                acc2[rr][2] = f2_fma(pp, v1.x, acc2[rr][2]);
                acc2[rr][3] = f2_fma(pp, v1.y, acc2[rr][3]);
                acc2[rr][4] = f2_fma(pp, v2.x, acc2[rr][4]);
                acc2[rr][5] = f2_fma(pp, v2.y, acc2[rr][5]);
                acc2[rr][6] = f2_fma(pp, v3.x, acc2[rr][6]);
                acc2[rr][7] = f2_fma(pp, v3.y, acc2[rr][7]);
            }
        }
        // no second barrier: double buffering separates writers/readers
    }

    // ---- write context ----
    #pragma unroll
    for (int rr = 0; rr < 2; ++rr) {
        float inv = 1.0f / sum[rr];
        float* outp = g_ctx + ((size_t)bt*Nc + r0 + rr)*Dc + h*HDc;
        #pragma unroll
        for (int j = 0; j < 4; ++j) {
            float lo0, hi0, lo1, hi1;
            f2_unpack(acc2[rr][2*j],   lo0, hi0);
            f2_unpack(acc2[rr][2*j+1], lo1, hi1);
            *(float4*)(outp + j*4) = make_float4(lo0*inv, hi0*inv, lo1*inv, hi1*inv);
        }
    }
}

// ============================================================
extern "C" void kernel_launch(void* const* d_in, const int* in_sizes, int n_in,
                              void* d_out, int out_size)
{
    const float* x   = (const float*)d_in[0];
    const float* adj = (const float*)d_in[1];
    const float* Wq  = (const float*)d_in[2];
    const float* bq  = (const float*)d_in[3];
    const float* Wk  = (const float*)d_in[4];
    const float* bk  = (const float*)d_in[5];
    const float* Wv  = (const float*)d_in[6];
    const float* bv  = (const float*)d_in[7];
    const float* Wo  = (const float*)d_in[8];
    const float* bo  = (const float*)d_in[9];
    float* out = (float*)d_out;

    const int smem_proj = 2 * 128 * 132 * sizeof(float);                    // 135168
    const int smem_attn = (2*Nc*HDc + 2*CHUNK*APAD) * sizeof(float);        // 196864
    cudaFuncSetAttribute(proj_qkv_kernel, cudaFuncAttributeMaxDynamicSharedMemorySize, smem_proj);
    cudaFuncSetAttribute(proj_o_kernel,   cudaFuncAttributeMaxDynamicSharedMemorySize, smem_proj);
    cudaFuncSetAttribute(attn_kernel,     cudaFuncAttributeMaxDynamicSharedMemorySize, smem_attn);

    dim3 gqkv(Mc/128, 3);
    proj_qkv_kernel<<<gqkv, 256, smem_proj>>>(x, Wq, bq, Wk, bk, Wv, bv);
    attn_kernel<<<BTc*Hc, 512, smem_attn>>>(adj);
    proj_o_kernel<<<Mc/128, 256, smem_proj>>>(Wo, bo, out);
}

// round 10
// speedup vs baseline: 1.4663x; 1.4663x over previous
#include <cuda_runtime.h>
#include <cuda_bf16.h>
#include <cstdint>

#define BTc 16
#define Nc 1024
#define Dc 128
#define Hc 8
#define HDc 16
#define Mc (BTc*Nc)

// ---- gmem scratch (no allocs allowed) ----
__device__ __nv_bfloat16 g_qh[(size_t)BTc*Hc*Nc*HDc];  // [slab][n][hd]
__device__ __nv_bfloat16 g_ql[(size_t)BTc*Hc*Nc*HDc];
__device__ __nv_bfloat16 g_kh[(size_t)BTc*Hc*Nc*HDc];
__device__ __nv_bfloat16 g_kl[(size_t)BTc*Hc*Nc*HDc];
__device__ __nv_bfloat16 g_vth[(size_t)BTc*Hc*HDc*Nc]; // [slab][hd][n] transposed
__device__ __nv_bfloat16 g_vtl[(size_t)BTc*Hc*HDc*Nc];
__device__ float g_ctx[(size_t)Mc*Dc];

typedef unsigned long long f2_t;
__device__ __forceinline__ f2_t f2_fma(f2_t a, f2_t b, f2_t c){ f2_t r; asm("fma.rn.f32x2 %0,%1,%2,%3;":"=l"(r):"l"(a),"l"(b),"l"(c)); return r; }
__device__ __forceinline__ f2_t f2_pack(float lo, float hi){ f2_t r; asm("mov.b64 %0,{%1,%2};":"=l"(r):"f"(lo),"f"(hi)); return r; }
__device__ __forceinline__ void f2_unpack(f2_t a, float& lo, float& hi){ asm("mov.b64 {%0,%1},%2;":"=f"(lo),"=f"(hi):"l"(a)); }
__device__ __forceinline__ float fast_ex2(float x){ float r; asm("ex2.approx.f32 %0,%1;":"=f"(r):"f"(x)); return r; }
__device__ __forceinline__ uint32_t smem_u32(const void* p){ uint32_t a; asm("{ .reg .u64 t; cvta.to.shared.u64 t, %1; cvt.u32.u64 %0, t; }":"=r"(a):"l"(p)); return a; }
__device__ __forceinline__ uint32_t packbf(float x, float y){
    __nv_bfloat162 t = __floats2bfloat162_rn(x, y);   // .x = low half
    return *reinterpret_cast<uint32_t*>(&t);
}
__device__ __forceinline__ void mma16816(float* d, uint32_t a0,uint32_t a1,uint32_t a2,uint32_t a3,
                                         uint32_t b0,uint32_t b1){
    asm volatile("mma.sync.aligned.m16n8k16.row.col.f32.bf16.bf16.f32 "
        "{%0,%1,%2,%3},{%4,%5,%6,%7},{%8,%9},{%0,%1,%2,%3};"
        : "+f"(d[0]),"+f"(d[1]),"+f"(d[2]),"+f"(d[3])
        : "r"(a0),"r"(a1),"r"(a2),"r"(a3),"r"(b0),"r"(b1));
}
#define CP16(dst,src) asm volatile("cp.async.ca.shared.global [%0], [%1], 16;"::"r"(dst),"l"(src):"memory")
#define CP_COMMIT()   asm volatile("cp.async.commit_group;":::"memory")
#define CP_WAIT0()    asm volatile("cp.async.wait_group 0;":::"memory")

// smem layout (bytes); strides: Q/K rows 24 bf16 (48B), Vt rows 136 bf16 (272B), adj rows 132 f32 (528B)
#define O_QH 0
#define O_QL 12288
#define O_KH 24576
#define O_KL 36864
#define O_VH 49152
#define O_VL 57856
#define O_ADJ 66560
#define SMEM_ATTN 201728   // O_ADJ + 2*67584

// ============================================================
// scalar projection GEMM (proven machinery)
// ============================================================
__device__ __forceinline__ void gemm_tile(const float* __restrict__ Xg, const float* __restrict__ Wg,
                                          float* Xs, float* Ws, f2_t acc2[8][4], int m0, int tid)
{
    #pragma unroll
    for (int it = 0; it < 16; ++it) {
        int idx = it*256 + tid; int m = idx >> 5, k4 = idx & 31;
        *(float4*)(Xs + m*132 + k4*4) = *(const float4*)(Xg + (size_t)(m0+m)*128 + k4*4);
        *(float4*)(Ws + m*132 + k4*4) = *(const float4*)(Wg + (size_t)m*128 + k4*4);
    }
    __syncthreads();
    int tx = tid & 15, ty = tid >> 4;
    #pragma unroll
    for (int i = 0; i < 8; ++i) { acc2[i][0]=0; acc2[i][1]=0; acc2[i][2]=0; acc2[i][3]=0; }
    #pragma unroll 4
    for (int k = 0; k < 128; ++k) {
        f2_t a2[8], b2[4];
        #pragma unroll
        for (int i = 0; i < 8; ++i) { float a = Xs[(ty*8+i)*132 + k]; a2[i] = f2_pack(a, a); }
        #pragma unroll
        for (int t = 0; t < 4; ++t) b2[t] = f2_pack(Ws[(tx+32*t)*132+k], Ws[(tx+32*t+16)*132+k]);
        #pragma unroll
        for (int i = 0; i < 8; ++i)
            #pragma unroll
            for (int t = 0; t < 4; ++t) acc2[i][t] = f2_fma(a2[i], b2[t], acc2[i][t]);
    }
}

__device__ __forceinline__ void store_qkv(int sel, int bt, int n, int j, float v)
{
    int head = j >> 4, hd = j & 15, slab = bt*Hc + head;
    __nv_bfloat16 hb = __float2bfloat16_rn(v);
    float hf = __bfloat162float(hb);
    __nv_bfloat16 lb = __float2bfloat16_rn(v - hf);
    if (sel == 0) { size_t i = ((size_t)slab*Nc + n)*HDc + hd; g_qh[i] = hb; g_ql[i] = lb; }
    else if (sel == 1) { size_t i = ((size_t)slab*Nc + n)*HDc + hd; g_kh[i] = hb; g_kl[i] = lb; }
    else { size_t i = (size_t)slab*HDc*Nc + (size_t)hd*Nc + n; g_vth[i] = hb; g_vtl[i] = lb; }
}

__global__ void __launch_bounds__(256) proj_qkv_kernel(
    const float* __restrict__ x,
    const float* __restrict__ Wq, const float* __restrict__ bq,
    const float* __restrict__ Wk, const float* __restrict__ bk,
    const float* __restrict__ Wv, const float* __restrict__ bv)
{
    extern __shared__ float sm[];
    float* Xs = sm; float* Ws = sm + 128*132;
    int sel = blockIdx.y;
    const float* W    = (sel==0)?Wq:(sel==1)?Wk:Wv;
    const float* bias = (sel==0)?bq:(sel==1)?bk:bv;
    float scale = (sel==0)?(0.25f*1.4426950408889634f):1.0f;
    int m0 = blockIdx.x * 128;
    f2_t acc2[8][4];
    gemm_tile(x, W, Xs, Ws, acc2, m0, threadIdx.x);
    int tx = threadIdx.x & 15, ty = threadIdx.x >> 4;
    int bt = m0 / Nc, nbase = m0 % Nc;
    #pragma unroll
    for (int i = 0; i < 8; ++i) {
        int n = nbase + ty*8 + i;
        #pragma unroll
        for (int t = 0; t < 4; ++t) {
            float lo, hi; f2_unpack(acc2[i][t], lo, hi);
            int j0 = tx + 32*t, j1 = j0 + 16;
            store_qkv(sel, bt, n, j0, (lo + bias[j0])*scale);
            store_qkv(sel, bt, n, j1, (hi + bias[j1])*scale);
        }
    }
}

__global__ void __launch_bounds__(256) proj_o_kernel(
    const float* __restrict__ Wo, const float* __restrict__ bo, float* __restrict__ out)
{
    extern __shared__ float sm[];
    float* Xs = sm; float* Ws = sm + 128*132;
    int m0 = blockIdx.x * 128;
    f2_t acc2[8][4];
    gemm_tile(g_ctx, Wo, Xs, Ws, acc2, m0, threadIdx.x);
    int tx = threadIdx.x & 15, ty = threadIdx.x >> 4;
    #pragma unroll
    for (int i = 0; i < 8; ++i) {
        size_t m = m0 + ty*8 + i;
        #pragma unroll
        for (int t = 0; t < 4; ++t) {
            float lo, hi; f2_unpack(acc2[i][t], lo, hi);
            int j0 = tx + 32*t, j1 = j0 + 16;
            out[m*Dc + j0] = lo + bo[j0];
            out[m*Dc + j1] = hi + bo[j1];
        }
    }
}

// ============================================================
// bf16x3 warp-MMA flash attention.  One CTA per (bt,h), 256 thr (8 warps).
// Warp w owns q-rows [w*16, w*16+16).  Per (qt 128-rows, ch 128-cols):
//   S = QhKh + QhKl + QlKh  (16 n8-tiles x 3 mma, k16 = full hd)
//   p = ex2(s)*adj  (S accum frags -> A frags in registers)
//   ctx += PhVh + PhVl + PlVh  (8 k-steps x 2 n8 x 3 mma)
// cp.async double-buffered K/V/adj/Q pipeline.
// ============================================================
__device__ __forceinline__ void issue_loads(int it, int t, uint32_t sb,
    const __nv_bfloat16* gqh, const __nv_bfloat16* gql,
    const __nv_bfloat16* gkh, const __nv_bfloat16* gkl,
    const __nv_bfloat16* gvh, const __nv_bfloat16* gvl,
    const float* adjg)
{
    int qt = it >> 3, ch = it & 7, b = it & 1;
    int row = t >> 1, hw = t & 1;
    CP16(sb + O_KH + b*6144 + row*48 + hw*16, gkh + (ch*128+row)*16 + hw*8);
    CP16(sb + O_KL + b*6144 + row*48 + hw*16, gkl + (ch*128+row)*16 + hw*8);
    int vg = t >> 4, vp = t & 15;
    CP16(sb + O_VH + b*4352 + vg*272 + vp*16, gvh + vg*1024 + ch*128 + vp*8);
    CP16(sb + O_VL + b*4352 + vg*272 + vp*16, gvl + vg*1024 + ch*128 + vp*8);
    #pragma unroll
    for (int i = 0; i < 16; ++i) {
        int e = i*256 + t, r2 = e >> 5, q4 = e & 31;   // 128 rows x 32 float4
        CP16(sb + O_ADJ + b*67584 + r2*528 + q4*16,
             adjg + (size_t)(qt*128 + r2)*1024 + ch*128 + q4*4);
    }
    if (ch == 0) {
        int qb = qt & 1;
        CP16(sb + O_QH + qb*6144 + row*48 + hw*16, gqh + (qt*128+row)*16 + hw*8);
        CP16(sb + O_QL + qb*6144 + row*48 + hw*16, gql + (qt*128+row)*16 + hw*8);
    }
    CP_COMMIT();
}

__global__ void __launch_bounds__(256,1) attn_mma_kernel(const float* __restrict__ adj)
{
    extern __shared__ char smc[];
    uint32_t sb = smem_u32(smc);
    int t = threadIdx.x, w = t >> 5, l = t & 31;
    int g = l >> 2, c2 = (l & 3)*2;
    int bt = blockIdx.x >> 3, h = blockIdx.x & 7, slab = bt*Hc + h;
    int m0 = w*16;

    const __nv_bfloat16* gqh = g_qh + (size_t)slab*Nc*HDc;
    const __nv_bfloat16* gql = g_ql + (size_t)slab*Nc*HDc;
    const __nv_bfloat16* gkh = g_kh + (size_t)slab*Nc*HDc;
    const __nv_bfloat16* gkl = g_kl + (size_t)slab*Nc*HDc;
    const __nv_bfloat16* gvh = g_vth + (size_t)slab*HDc*Nc;
    const __nv_bfloat16* gvl = g_vtl + (size_t)slab*HDc*Nc;
    const float* adjg = adj + ((size_t)bt << 20);

    uint32_t qh0=0,qh1=0,qh2=0,qh3=0, ql0=0,ql1=0,ql2=0,ql3=0;
    float ctx0[4], ctx1[4], sum0 = 0.f, sum1 = 0.f;

    issue_loads(0, t, sb, gqh, gql, gkh, gkl, gvh, gvl, adjg);

    for (int it = 0; it < 64; ++it) {
        CP_WAIT0();
        __syncthreads();
        if (it < 63) issue_loads(it+1, t, sb, gqh, gql, gkh, gkl, gvh, gvl, adjg);

        int qt = it >> 3, ch = it & 7, b = it & 1;
        const __nv_bfloat16* sKh = (const __nv_bfloat16*)(smc + O_KH + b*6144);
        const __nv_bfloat16* sKl = (const __nv_bfloat16*)(smc + O_KL + b*6144);
        const __nv_bfloat16* sVh = (const __nv_bfloat16*)(smc + O_VH + b*4352);
        const __nv_bfloat16* sVl = (const __nv_bfloat16*)(smc + O_VL + b*4352);
        const float* sAdj = (const float*)(smc + O_ADJ + b*67584);

        if (ch == 0) {
            const __nv_bfloat16* sQh = (const __nv_bfloat16*)(smc + O_QH + (qt&1)*6144);
            const __nv_bfloat16* sQl = (const __nv_bfloat16*)(smc + O_QL + (qt&1)*6144);
            qh0 = *(const uint32_t*)(sQh + (m0+g)*24 + c2);
            qh1 = *(const uint32_t*)(sQh + (m0+g+8)*24 + c2);
            qh2 = *(const uint32_t*)(sQh + (m0+g)*24 + c2 + 8);
            qh3 = *(const uint32_t*)(sQh + (m0+g+8)*24 + c2 + 8);
            ql0 = *(const uint32_t*)(sQl + (m0+g)*24 + c2);
            ql1 = *(const uint32_t*)(sQl + (m0+g+8)*24 + c2);
            ql2 = *(const uint32_t*)(sQl + (m0+g)*24 + c2 + 8);
            ql3 = *(const uint32_t*)(sQl + (m0+g+8)*24 + c2 + 8);
            ctx0[0]=ctx0[1]=ctx0[2]=ctx0[3]=0.f;
            ctx1[0]=ctx1[1]=ctx1[2]=ctx1[3]=0.f;
            sum0 = 0.f; sum1 = 0.f;
        }

        // ---- S = Q K^T (bf16x3) ----
        float sacc[16][4];
        #pragma unroll
        for (int j = 0; j < 16; ++j) { sacc[j][0]=0.f; sacc[j][1]=0.f; sacc[j][2]=0.f; sacc[j][3]=0.f; }
        #pragma unroll
        for (int j = 0; j < 16; ++j) {
            int n0 = 8*j;
            uint32_t bh0 = *(const uint32_t*)(sKh + (n0+g)*24 + c2);
            uint32_t bh1 = *(const uint32_t*)(sKh + (n0+g)*24 + c2 + 8);
            uint32_t bl0 = *(const uint32_t*)(sKl + (n0+g)*24 + c2);
            uint32_t bl1 = *(const uint32_t*)(sKl + (n0+g)*24 + c2 + 8);
            mma16816(sacc[j], qh0,qh1,qh2,qh3, bh0,bh1);
            mma16816(sacc[j], qh0,qh1,qh2,qh3, bl0,bl1);
            mma16816(sacc[j], ql0,ql1,ql2,ql3, bh0,bh1);
        }

        // ---- epilogue: p = ex2(s)*adj, split to bf16 hi/lo A-frags ----
        uint32_t phA[16], phB[16], plA[16], plB[16];
        #pragma unroll
        for (int j = 0; j < 16; ++j) {
            float2 aA = *(const float2*)(sAdj + (m0+g)*132 + 8*j + c2);
            float2 aB = *(const float2*)(sAdj + (m0+g+8)*132 + 8*j + c2);
            float p0 = fast_ex2(sacc[j][0]) * aA.x;
            float p1 = fast_ex2(sacc[j][1]) * aA.y;
            float p2 = fast_ex2(sacc[j][2]) * aB.x;
            float p3 = fast_ex2(sacc[j][3]) * aB.y;
            sum0 += p0 + p1; sum1 += p2 + p3;
            uint32_t hA = packbf(p0, p1), hB = packbf(p2, p3);
            phA[j] = hA; phB[j] = hB;
            plA[j] = packbf(p0 - __uint_as_float(hA << 16), p1 - __uint_as_float(hA & 0xffff0000u));
            plB[j] = packbf(p2 - __uint_as_float(hB << 16), p3 - __uint_as_float(hB & 0xffff0000u));
        }

        // ---- ctx += P V (bf16x3) ----
        #pragma unroll
        for (int kk = 0; kk < 8; ++kk) {
            int k0 = 16*kk;
            uint32_t vh0 = *(const uint32_t*)(sVh + g*136 + k0 + c2);
            uint32_t vh1 = *(const uint32_t*)(sVh + g*136 + k0 + c2 + 8);
            uint32_t vl0 = *(const uint32_t*)(sVl + g*136 + k0 + c2);
            uint32_t vl1 = *(const uint32_t*)(sVl + g*136 + k0 + c2 + 8);
            uint32_t wh0 = *(const uint32_t*)(sVh + (g+8)*136 + k0 + c2);
            uint32_t wh1 = *(const uint32_t*)(sVh + (g+8)*136 + k0 + c2 + 8);
            uint32_t wl0 = *(const uint32_t*)(sVl + (g+8)*136 + k0 + c2);
            uint32_t wl1 = *(const uint32_t*)(sVl + (g+8)*136 + k0 + c2 + 8);
            uint32_t a0 = phA[2*kk], a1 = phB[2*kk], a2 = phA[2*kk+1], a3 = phB[2*kk+1];
            uint32_t e0 = plA[2*kk], e1 = plB[2*kk], e2 = plA[2*kk+1], e3 = plB[2*kk+1];
            mma16816(ctx0, a0,a1,a2,a3, vh0,vh1);
            mma16816(ctx0, a0,a1,a2,a3, vl0,vl1);
            mma16816(ctx0, e0,e1,e2,e3, vh0,vh1);
            mma16816(ctx1, a0,a1,a2,a3, wh0,wh1);
            mma16816(ctx1, a0,a1,a2,a3, wl0,wl1);
            mma16816(ctx1, e0,e1,e2,e3, wh0,wh1);
        }

        if (ch == 7) {
            float s0 = sum0, s1 = sum1;
            s0 += __shfl_xor_sync(0xffffffffu, s0, 1);
            s0 += __shfl_xor_sync(0xffffffffu, s0, 2);
            s1 += __shfl_xor_sync(0xffffffffu, s1, 1);
            s1 += __shfl_xor_sync(0xffffffffu, s1, 2);
            float inv0 = 1.0f / (s0 + 1e-8f), inv1 = 1.0f / (s1 + 1e-8f);
            int qr = qt*128 + m0 + g;
            float* op  = g_ctx + ((size_t)(bt*Nc + qr))*Dc + h*HDc;
            float* op2 = op + 8*Dc;
            float2 o;
            o.x = ctx0[0]*inv0; o.y = ctx0[1]*inv0; *(float2*)(op + c2) = o;
            o.x = ctx1[0]*inv0; o.y = ctx1[1]*inv0; *(float2*)(op + 8 + c2) = o;
            o.x = ctx0[2]*inv1; o.y = ctx0[3]*inv1; *(float2*)(op2 + c2) = o;
            o.x = ctx1[2]*inv1; o.y = ctx1[3]*inv1; *(float2*)(op2 + 8 + c2) = o;
        }
    }
}

// ============================================================
extern "C" void kernel_launch(void* const* d_in, const int* in_sizes, int n_in,
                              void* d_out, int out_size)
{
    const float* x   = (const float*)d_in[0];
    const float* adj = (const float*)d_in[1];
    const float* Wq  = (const float*)d_in[2];
    const float* bq  = (const float*)d_in[3];
    const float* Wk  = (const float*)d_in[4];
    const float* bk  = (const float*)d_in[5];
    const float* Wv  = (const float*)d_in[6];
    const float* bv  = (const float*)d_in[7];
    const float* Wo  = (const float*)d_in[8];
    const float* bo  = (const float*)d_in[9];
    float* out = (float*)d_out;

    const int smem_proj = 2 * 128 * 132 * sizeof(float);
    cudaFuncSetAttribute(proj_qkv_kernel, cudaFuncAttributeMaxDynamicSharedMemorySize, smem_proj);
    cudaFuncSetAttribute(proj_o_kernel,   cudaFuncAttributeMaxDynamicSharedMemorySize, smem_proj);
    cudaFuncSetAttribute(attn_mma_kernel, cudaFuncAttributeMaxDynamicSharedMemorySize, SMEM_ATTN);

    dim3 gqkv(Mc/128, 3);
    proj_qkv_kernel<<<gqkv, 256, smem_proj>>>(x, Wq, bq, Wk, bk, Wv, bv);
    attn_mma_kernel<<<BTc*Hc, 256, SMEM_ATTN>>>(adj);
    proj_o_kernel<<<Mc/128, 256, smem_proj>>>(Wo, bo, out);
}

// round 11
// speedup vs baseline: 1.6301x; 1.1117x over previous
#include <cuda_runtime.h>
#include <cuda_bf16.h>
#include <cstdint>

#define BTc 16
#define Nc 1024
#define Dc 128
#define Hc 8
#define HDc 16
#define Mc (BTc*Nc)

// ---- gmem scratch (no allocs allowed) ----
__device__ __nv_bfloat16 g_qh[(size_t)BTc*Hc*Nc*HDc];  // [slab][n][hd]
__device__ __nv_bfloat16 g_ql[(size_t)BTc*Hc*Nc*HDc];
__device__ __nv_bfloat16 g_kh[(size_t)BTc*Hc*Nc*HDc];
__device__ __nv_bfloat16 g_kl[(size_t)BTc*Hc*Nc*HDc];
__device__ __nv_bfloat16 g_vth[(size_t)BTc*Hc*HDc*Nc]; // [slab][hd][n] transposed
__device__ __nv_bfloat16 g_vtl[(size_t)BTc*Hc*HDc*Nc];
__device__ float g_ctx[(size_t)Mc*Dc];

typedef unsigned long long f2_t;
__device__ __forceinline__ f2_t f2_fma(f2_t a, f2_t b, f2_t c){ f2_t r; asm("fma.rn.f32x2 %0,%1,%2,%3;":"=l"(r):"l"(a),"l"(b),"l"(c)); return r; }
__device__ __forceinline__ f2_t f2_pack(float lo, float hi){ f2_t r; asm("mov.b64 %0,{%1,%2};":"=l"(r):"f"(lo),"f"(hi)); return r; }
__device__ __forceinline__ void f2_unpack(f2_t a, float& lo, float& hi){ asm("mov.b64 {%0,%1},%2;":"=f"(lo),"=f"(hi):"l"(a)); }
__device__ __forceinline__ float fast_ex2(float x){ float r; asm("ex2.approx.f32 %0,%1;":"=f"(r):"f"(x)); return r; }
__device__ __forceinline__ uint32_t smem_u32(const void* p){ uint32_t a; asm("{ .reg .u64 t; cvta.to.shared.u64 t, %1; cvt.u32.u64 %0, t; }":"=r"(a):"l"(p)); return a; }
__device__ __forceinline__ uint32_t packbf(float x, float y){
    __nv_bfloat162 t = __floats2bfloat162_rn(x, y);   // .x = low half
    return *reinterpret_cast<uint32_t*>(&t);
}
__device__ __forceinline__ void mma16816(float* d, uint32_t a0,uint32_t a1,uint32_t a2,uint32_t a3,
                                         uint32_t b0,uint32_t b1){
    asm volatile("mma.sync.aligned.m16n8k16.row.col.f32.bf16.bf16.f32 "
        "{%0,%1,%2,%3},{%4,%5,%6,%7},{%8,%9},{%0,%1,%2,%3};"
        : "+f"(d[0]),"+f"(d[1]),"+f"(d[2]),"+f"(d[3])
        : "r"(a0),"r"(a1),"r"(a2),"r"(a3),"r"(b0),"r"(b1));
}
#define CP16(dst,src) asm volatile("cp.async.ca.shared.global [%0], [%1], 16;"::"r"(dst),"l"(src):"memory")
#define CP_COMMIT()   asm volatile("cp.async.commit_group;":::"memory")
#define CP_WAIT0()    asm volatile("cp.async.wait_group 0;":::"memory")

// attention smem layout (bytes)
#define O_QH 0
#define O_QL 12288
#define O_KH 24576
#define O_KL 36864
#define O_VH 49152
#define O_VL 57856
#define O_ADJ 66560
#define SMEM_ATTN 201728   // O_ADJ + 2*67584

// ============================================================
// scalar projection GEMM (proven machinery)
// ============================================================
__device__ __forceinline__ void gemm_tile(const float* __restrict__ Xg, const float* __restrict__ Wg,
                                          float* Xs, float* Ws, f2_t acc2[8][4], int m0, int tid)
{
    #pragma unroll
    for (int it = 0; it < 16; ++it) {
        int idx = it*256 + tid; int m = idx >> 5, k4 = idx & 31;
        *(float4*)(Xs + m*132 + k4*4) = *(const float4*)(Xg + (size_t)(m0+m)*128 + k4*4);
        *(float4*)(Ws + m*132 + k4*4) = *(const float4*)(Wg + (size_t)m*128 + k4*4);
    }
    __syncthreads();
    int tx = tid & 15, ty = tid >> 4;
    #pragma unroll
    for (int i = 0; i < 8; ++i) { acc2[i][0]=0; acc2[i][1]=0; acc2[i][2]=0; acc2[i][3]=0; }
    #pragma unroll 4
    for (int k = 0; k < 128; ++k) {
        f2_t a2[8], b2[4];
        #pragma unroll
        for (int i = 0; i < 8; ++i) { float a = Xs[(ty*8+i)*132 + k]; a2[i] = f2_pack(a, a); }
        #pragma unroll
        for (int t = 0; t < 4; ++t) b2[t] = f2_pack(Ws[(tx+32*t)*132+k], Ws[(tx+32*t+16)*132+k]);
        #pragma unroll
        for (int i = 0; i < 8; ++i)
            #pragma unroll
            for (int t = 0; t < 4; ++t) acc2[i][t] = f2_fma(a2[i], b2[t], acc2[i][t]);
    }
}

// ============================================================
// QKV projection with SMEM-staged, fully-coalesced bf16 hi/lo stores.
// Staging layout (bf16, 16384 elems each for hi/lo):
//   q,k: head*2048 + nl*16 + hd          (matches [slab][n][hd])
//   v:   head*2048 + hd*128 + nl         (matches [slab][hd][n] transposed)
// Then 2048 uint4 per buffer, 8/thread, contiguous per head in gmem.
// ============================================================
__global__ void __launch_bounds__(256) proj_qkv_kernel(
    const float* __restrict__ x,
    const float* __restrict__ Wq, const float* __restrict__ bq,
    const float* __restrict__ Wk, const float* __restrict__ bk,
    const float* __restrict__ Wv, const float* __restrict__ bv)
{
    extern __shared__ float sm[];
    float* Xs = sm; float* Ws = sm + 128*132;
    int sel = blockIdx.y;
    const float* W    = (sel==0)?Wq:(sel==1)?Wk:Wv;
    const float* bias = (sel==0)?bq:(sel==1)?bk:bv;
    float scale = (sel==0)?(0.25f*1.4426950408889634f):1.0f;
    int m0 = blockIdx.x * 128;
    f2_t acc2[8][4];
    gemm_tile(x, W, Xs, Ws, acc2, m0, threadIdx.x);
    __syncthreads();   // done reading Xs/Ws; reuse as staging

    __nv_bfloat16* Sh = (__nv_bfloat16*)sm;
    __nv_bfloat16* Sl = Sh + 16384;

    int tx = threadIdx.x & 15, ty = threadIdx.x >> 4;
    int bt = m0 / Nc, nbase = m0 % Nc;
    #pragma unroll
    for (int i = 0; i < 8; ++i) {
        int nl = ty*8 + i;
        #pragma unroll
        for (int t = 0; t < 4; ++t) {
            float lo, hi; f2_unpack(acc2[i][t], lo, hi);
            int j0 = tx + 32*t, j1 = j0 + 16;
            float v0 = (lo + bias[j0])*scale;
            float v1 = (hi + bias[j1])*scale;
            #pragma unroll
            for (int s = 0; s < 2; ++s) {
                int j = s ? j1 : j0;
                float v = s ? v1 : v0;
                __nv_bfloat16 hb = __float2bfloat16_rn(v);
                __nv_bfloat16 lb = __float2bfloat16_rn(v - __bfloat162float(hb));
                int head = j >> 4, hd = j & 15;
                int off = (sel < 2) ? (head*2048 + nl*16 + hd)
                                    : (head*2048 + hd*128 + nl);
                Sh[off] = hb; Sl[off] = lb;
            }
        }
    }
    __syncthreads();

    __nv_bfloat16* GH = (sel==0)?g_qh:(sel==1)?g_kh:g_vth;
    __nv_bfloat16* GL = (sel==0)?g_ql:(sel==1)?g_kl:g_vtl;
    const uint4* sh4 = (const uint4*)Sh;
    const uint4* sl4 = (const uint4*)Sl;
    #pragma unroll
    for (int it = 0; it < 8; ++it) {
        int i4 = it*256 + threadIdx.x;          // 0..2047
        int head = i4 >> 8, rem = i4 & 255;     // 256 uint4 per head
        size_t gbase;
        if (sel < 2) {
            // per head: 128 rows x 16 bf16 contiguous at [(slab*1024+nbase)*16]
            gbase = (((size_t)(bt*Hc + head))*Nc + nbase)*HDc;
            ((uint4*)(GH + gbase))[rem] = sh4[i4];
            ((uint4*)(GL + gbase))[rem] = sl4[i4];
        } else {
            // per (head,hd): 128 bf16 contiguous at [slab*16*1024 + hd*1024 + nbase]
            int hd = rem >> 4, n8 = rem & 15;
            gbase = ((size_t)(bt*Hc + head))*HDc*Nc + (size_t)hd*Nc + nbase;
            ((uint4*)(GH + gbase))[n8] = sh4[i4];
            ((uint4*)(GL + gbase))[n8] = sl4[i4];
        }
    }
}

__global__ void __launch_bounds__(256) proj_o_kernel(
    const float* __restrict__ Wo, const float* __restrict__ bo, float* __restrict__ out)
{
    extern __shared__ float sm[];
    float* Xs = sm; float* Ws = sm + 128*132;
    int m0 = blockIdx.x * 128;
    f2_t acc2[8][4];
    gemm_tile(g_ctx, Wo, Xs, Ws, acc2, m0, threadIdx.x);
    int tx = threadIdx.x & 15, ty = threadIdx.x >> 4;
    #pragma unroll
    for (int i = 0; i < 8; ++i) {
        size_t m = m0 + ty*8 + i;
        #pragma unroll
        for (int t = 0; t < 4; ++t) {
            float lo, hi; f2_unpack(acc2[i][t], lo, hi);
            int j0 = tx + 32*t, j1 = j0 + 16;
            out[m*Dc + j0] = lo + bo[j0];
            out[m*Dc + j1] = hi + bo[j1];
        }
    }
}

// ============================================================
// bf16x3 warp-MMA flash attention (UNCHANGED from the 299us version)
// ============================================================
__device__ __forceinline__ void issue_loads(int it, int t, uint32_t sb,
    const __nv_bfloat16* gqh, const __nv_bfloat16* gql,
    const __nv_bfloat16* gkh, const __nv_bfloat16* gkl,
    const __nv_bfloat16* gvh, const __nv_bfloat16* gvl,
    const float* adjg)
{
    int qt = it >> 3, ch = it & 7, b = it & 1;
    int row = t >> 1, hw = t & 1;
    CP16(sb + O_KH + b*6144 + row*48 + hw*16, gkh + (ch*128+row)*16 + hw*8);
    CP16(sb + O_KL + b*6144 + row*48 + hw*16, gkl + (ch*128+row)*16 + hw*8);
    int vg = t >> 4, vp = t & 15;
    CP16(sb + O_VH + b*4352 + vg*272 + vp*16, gvh + vg*1024 + ch*128 + vp*8);
    CP16(sb + O_VL + b*4352 + vg*272 + vp*16, gvl + vg*1024 + ch*128 + vp*8);
    #pragma unroll
    for (int i = 0; i < 16; ++i) {
        int e = i*256 + t, r2 = e >> 5, q4 = e & 31;   // 128 rows x 32 float4
        CP16(sb + O_ADJ + b*67584 + r2*528 + q4*16,
             adjg + (size_t)(qt*128 + r2)*1024 + ch*128 + q4*4);
    }
    if (ch == 0) {
        int qb = qt & 1;
        CP16(sb + O_QH + qb*6144 + row*48 + hw*16, gqh + (qt*128+row)*16 + hw*8);
        CP16(sb + O_QL + qb*6144 + row*48 + hw*16, gql + (qt*128+row)*16 + hw*8);
    }
    CP_COMMIT();
}

__global__ void __launch_bounds__(256,1) attn_mma_kernel(const float* __restrict__ adj)
{
    extern __shared__ char smc[];
    uint32_t sb = smem_u32(smc);
    int t = threadIdx.x, w = t >> 5, l = t & 31;
    int g = l >> 2, c2 = (l & 3)*2;
    int bt = blockIdx.x >> 3, h = blockIdx.x & 7, slab = bt*Hc + h;
    int m0 = w*16;

    const __nv_bfloat16* gqh = g_qh + (size_t)slab*Nc*HDc;
    const __nv_bfloat16* gql = g_ql + (size_t)slab*Nc*HDc;
    const __nv_bfloat16* gkh = g_kh + (size_t)slab*Nc*HDc;
    const __nv_bfloat16* gkl = g_kl + (size_t)slab*Nc*HDc;
    const __nv_bfloat16* gvh = g_vth + (size_t)slab*HDc*Nc;
    const __nv_bfloat16* gvl = g_vtl + (size_t)slab*HDc*Nc;
    const float* adjg = adj + ((size_t)bt << 20);

    uint32_t qh0=0,qh1=0,qh2=0,qh3=0, ql0=0,ql1=0,ql2=0,ql3=0;
    float ctx0[4], ctx1[4], sum0 = 0.f, sum1 = 0.f;

    issue_loads(0, t, sb, gqh, gql, gkh, gkl, gvh, gvl, adjg);

    for (int it = 0; it < 64; ++it) {
        CP_WAIT0();
        __syncthreads();
        if (it < 63) issue_loads(it+1, t, sb, gqh, gql, gkh, gkl, gvh, gvl, adjg);

        int qt = it >> 3, ch = it & 7, b = it & 1;
        const __nv_bfloat16* sKh = (const __nv_bfloat16*)(smc + O_KH + b*6144);
        const __nv_bfloat16* sKl = (const __nv_bfloat16*)(smc + O_KL + b*6144);
        const __nv_bfloat16* sVh = (const __nv_bfloat16*)(smc + O_VH + b*4352);
        const __nv_bfloat16* sVl = (const __nv_bfloat16*)(smc + O_VL + b*4352);
        const float* sAdj = (const float*)(smc + O_ADJ + b*67584);

        if (ch == 0) {
            const __nv_bfloat16* sQh = (const __nv_bfloat16*)(smc + O_QH + (qt&1)*6144);
            const __nv_bfloat16* sQl = (const __nv_bfloat16*)(smc + O_QL + (qt&1)*6144);
            qh0 = *(const uint32_t*)(sQh + (m0+g)*24 + c2);
            qh1 = *(const uint32_t*)(sQh + (m0+g+8)*24 + c2);
            qh2 = *(const uint32_t*)(sQh + (m0+g)*24 + c2 + 8);
            qh3 = *(const uint32_t*)(sQh + (m0+g+8)*24 + c2 + 8);
            ql0 = *(const uint32_t*)(sQl + (m0+g)*24 + c2);
            ql1 = *(const uint32_t*)(sQl + (m0+g+8)*24 + c2);
            ql2 = *(const uint32_t*)(sQl + (m0+g)*24 + c2 + 8);
            ql3 = *(const uint32_t*)(sQl + (m0+g+8)*24 + c2 + 8);
            ctx0[0]=ctx0[1]=ctx0[2]=ctx0[3]=0.f;
            ctx1[0]=ctx1[1]=ctx1[2]=ctx1[3]=0.f;
            sum0 = 0.f; sum1 = 0.f;
        }

        // ---- S = Q K^T (bf16x3) ----
        float sacc[16][4];
        #pragma unroll
        for (int j = 0; j < 16; ++j) { sacc[j][0]=0.f; sacc[j][1]=0.f; sacc[j][2]=0.f; sacc[j][3]=0.f; }
        #pragma unroll
        for (int j = 0; j < 16; ++j) {
            int n0 = 8*j;
            uint32_t bh0 = *(const uint32_t*)(sKh + (n0+g)*24 + c2);
            uint32_t bh1 = *(const uint32_t*)(sKh + (n0+g)*24 + c2 + 8);
            uint32_t bl0 = *(const uint32_t*)(sKl + (n0+g)*24 + c2);
            uint32_t bl1 = *(const uint32_t*)(sKl + (n0+g)*24 + c2 + 8);
            mma16816(sacc[j], qh0,qh1,qh2,qh3, bh0,bh1);
            mma16816(sacc[j], qh0,qh1,qh2,qh3, bl0,bl1);
            mma16816(sacc[j], ql0,ql1,ql2,ql3, bh0,bh1);
        }

        // ---- epilogue: p = ex2(s)*adj, split to bf16 hi/lo A-frags ----
        uint32_t phA[16], phB[16], plA[16], plB[16];
        #pragma unroll
        for (int j = 0; j < 16; ++j) {
            float2 aA = *(const float2*)(sAdj + (m0+g)*132 + 8*j + c2);
            float2 aB = *(const float2*)(sAdj + (m0+g+8)*132 + 8*j + c2);
            float p0 = fast_ex2(sacc[j][0]) * aA.x;
            float p1 = fast_ex2(sacc[j][1]) * aA.y;
            float p2 = fast_ex2(sacc[j][2]) * aB.x;
            float p3 = fast_ex2(sacc[j][3]) * aB.y;
            sum0 += p0 + p1; sum1 += p2 + p3;
            uint32_t hA = packbf(p0, p1), hB = packbf(p2, p3);
            phA[j] = hA; phB[j] = hB;
            plA[j] = packbf(p0 - __uint_as_float(hA << 16), p1 - __uint_as_float(hA & 0xffff0000u));
            plB[j] = packbf(p2 - __uint_as_float(hB << 16), p3 - __uint_as_float(hB & 0xffff0000u));
        }

        // ---- ctx += P V (bf16x3) ----
        #pragma unroll
        for (int kk = 0; kk < 8; ++kk) {
            int k0 = 16*kk;
            uint32_t vh0 = *(const uint32_t*)(sVh + g*136 + k0 + c2);
            uint32_t vh1 = *(const uint32_t*)(sVh + g*136 + k0 + c2 + 8);
            uint32_t vl0 = *(const uint32_t*)(sVl + g*136 + k0 + c2);
            uint32_t vl1 = *(const uint32_t*)(sVl + g*136 + k0 + c2 + 8);
            uint32_t wh0 = *(const uint32_t*)(sVh + (g+8)*136 + k0 + c2);
            uint32_t wh1 = *(const uint32_t*)(sVh + (g+8)*136 + k0 + c2 + 8);
            uint32_t wl0 = *(const uint32_t*)(sVl + (g+8)*136 + k0 + c2);
            uint32_t wl1 = *(const uint32_t*)(sVl + (g+8)*136 + k0 + c2 + 8);
            uint32_t a0 = phA[2*kk], a1 = phB[2*kk], a2 = phA[2*kk+1], a3 = phB[2*kk+1];
            uint32_t e0 = plA[2*kk], e1 = plB[2*kk], e2 = plA[2*kk+1], e3 = plB[2*kk+1];
            mma16816(ctx0, a0,a1,a2,a3, vh0,vh1);
            mma16816(ctx0, a0,a1,a2,a3, vl0,vl1);
            mma16816(ctx0, e0,e1,e2,e3, vh0,vh1);
            mma16816(ctx1, a0,a1,a2,a3, wh0,wh1);
            mma16816(ctx1, a0,a1,a2,a3, wl0,wl1);
            mma16816(ctx1, e0,e1,e2,e3, wh0,wh1);
        }

        if (ch == 7) {
            float s0 = sum0, s1 = sum1;
            s0 += __shfl_xor_sync(0xffffffffu, s0, 1);
            s0 += __shfl_xor_sync(0xffffffffu, s0, 2);
            s1 += __shfl_xor_sync(0xffffffffu, s1, 1);
            s1 += __shfl_xor_sync(0xffffffffu, s1, 2);
            float inv0 = 1.0f / (s0 + 1e-8f), inv1 = 1.0f / (s1 + 1e-8f);
            int qr = qt*128 + m0 + g;
            float* op  = g_ctx + ((size_t)(bt*Nc + qr))*Dc + h*HDc;
            float* op2 = op + 8*Dc;
            float2 o;
            o.x = ctx0[0]*inv0; o.y = ctx0[1]*inv0; *(float2*)(op + c2) = o;
            o.x = ctx1[0]*inv0; o.y = ctx1[1]*inv0; *(float2*)(op + 8 + c2) = o;
            o.x = ctx0[2]*inv1; o.y = ctx0[3]*inv1; *(float2*)(op2 + c2) = o;
            o.x = ctx1[2]*inv1; o.y = ctx1[3]*inv1; *(float2*)(op2 + 8 + c2) = o;
        }
    }
}

// ============================================================
extern "C" void kernel_launch(void* const* d_in, const int* in_sizes, int n_in,
                              void* d_out, int out_size)
{
    const float* x   = (const float*)d_in[0];
    const float* adj = (const float*)d_in[1];
    const float* Wq  = (const float*)d_in[2];
    const float* bq  = (const float*)d_in[3];
    const float* Wk  = (const float*)d_in[4];
    const float* bk  = (const float*)d_in[5];
    const float* Wv  = (const float*)d_in[6];
    const float* bv  = (const float*)d_in[7];
    const float* Wo  = (const float*)d_in[8];
    const float* bo  = (const float*)d_in[9];
    float* out = (float*)d_out;

    const int smem_proj = 2 * 128 * 132 * sizeof(float);
    cudaFuncSetAttribute(proj_qkv_kernel, cudaFuncAttributeMaxDynamicSharedMemorySize, smem_proj);
    cudaFuncSetAttribute(proj_o_kernel,   cudaFuncAttributeMaxDynamicSharedMemorySize, smem_proj);
    cudaFuncSetAttribute(attn_mma_kernel, cudaFuncAttributeMaxDynamicSharedMemorySize, SMEM_ATTN);

    dim3 gqkv(Mc/128, 3);
    proj_qkv_kernel<<<gqkv, 256, smem_proj>>>(x, Wq, bq, Wk, bk, Wv, bv);
    attn_mma_kernel<<<BTc*Hc, 256, SMEM_ATTN>>>(adj);
    proj_o_kernel<<<Mc/128, 256, smem_proj>>>(Wo, bo, out);
}

// round 12
// speedup vs baseline: 2.0941x; 1.2847x over previous
#include <cuda_runtime.h>
#include <cuda_bf16.h>
#include <cstdint>

#define BTc 16
#define Nc 1024
#define Dc 128
#define Hc 8
#define HDc 16
#define Mc (BTc*Nc)

// ---- gmem scratch (no allocs allowed) ----
__device__ __nv_bfloat16 g_qh[(size_t)BTc*Hc*Nc*HDc];  // [slab][n][hd]
__device__ __nv_bfloat16 g_ql[(size_t)BTc*Hc*Nc*HDc];
__device__ __nv_bfloat16 g_kh[(size_t)BTc*Hc*Nc*HDc];
__device__ __nv_bfloat16 g_kl[(size_t)BTc*Hc*Nc*HDc];
__device__ __nv_bfloat16 g_vth[(size_t)BTc*Hc*HDc*Nc]; // [slab][hd][n] transposed
__device__ __nv_bfloat16 g_vtl[(size_t)BTc*Hc*HDc*Nc];
__device__ float g_ctx[(size_t)Mc*Dc];

__device__ __forceinline__ float fast_ex2(float x){ float r; asm("ex2.approx.f32 %0,%1;":"=f"(r):"f"(x)); return r; }
__device__ __forceinline__ uint32_t smem_u32(const void* p){ uint32_t a; asm("{ .reg .u64 t; cvta.to.shared.u64 t, %1; cvt.u32.u64 %0, t; }":"=r"(a):"l"(p)); return a; }
__device__ __forceinline__ uint32_t packbf(float x, float y){
    __nv_bfloat162 t = __floats2bfloat162_rn(x, y);   // .x = low half
    return *reinterpret_cast<uint32_t*>(&t);
}
__device__ __forceinline__ void mma16816(float* d, uint32_t a0,uint32_t a1,uint32_t a2,uint32_t a3,
                                         uint32_t b0,uint32_t b1){
    asm volatile("mma.sync.aligned.m16n8k16.row.col.f32.bf16.bf16.f32 "
        "{%0,%1,%2,%3},{%4,%5,%6,%7},{%8,%9},{%0,%1,%2,%3};"
        : "+f"(d[0]),"+f"(d[1]),"+f"(d[2]),"+f"(d[3])
        : "r"(a0),"r"(a1),"r"(a2),"r"(a3),"r"(b0),"r"(b1));
}
#define CP16(dst,src) asm volatile("cp.async.ca.shared.global [%0], [%1], 16;"::"r"(dst),"l"(src):"memory")
#define CP_COMMIT()   asm volatile("cp.async.commit_group;":::"memory")
#define CP_WAIT0()    asm volatile("cp.async.wait_group 0;":::"memory")

// attention smem layout (bytes)
#define O_QH 0
#define O_QL 12288
#define O_KH 24576
#define O_KL 36864
#define O_VH 49152
#define O_VL 57856
#define O_ADJ 66560
#define SMEM_ATTN 201728   // O_ADJ + 2*67584

// projection smem layout (bytes); tiles stride 136 bf16 = 272B/row
#define SPITCH 136
#define P_XH 0
#define P_XL 34816
#define P_WH 69632
#define P_WL 104448
#define P_BIAS 139264
#define SMEM_PROJ 139776

// ============================================================
// Shared mma GEMM tile: C[128,128] = X[128,128] @ W[128,128]^T (bf16x3).
// Loads+converts X,W f32->bf16 hi/lo smem, computes per-warp 16x128.
// acc[j][0..3]: (row m0w+g, col 8j+c2), (row.., col+1), (row+8, ..), (row+8, +1)
// ============================================================
__device__ __forceinline__ void proj_mma_tile(const float* __restrict__ Xg,
                                              const float* __restrict__ Wg,
                                              const float* __restrict__ bias,
                                              char* smc, int m0, float acc[16][4])
{
    int tid = threadIdx.x;
    __nv_bfloat16* Xh = (__nv_bfloat16*)(smc + P_XH);
    __nv_bfloat16* Xl = (__nv_bfloat16*)(smc + P_XL);
    __nv_bfloat16* Wh = (__nv_bfloat16*)(smc + P_WH);
    __nv_bfloat16* Wl = (__nv_bfloat16*)(smc + P_WL);
    float* bias_s = (float*)(smc + P_BIAS);
    if (tid < 128) bias_s[tid] = bias[tid];

    #pragma unroll
    for (int it = 0; it < 16; ++it) {
        int idx = it*256 + tid; int m = idx >> 5, k4 = (idx & 31)*4;
        float4 v = *(const float4*)(Xg + (size_t)(m0+m)*128 + k4);
        uint32_t H0 = packbf(v.x, v.y), H1 = packbf(v.z, v.w);
        float r0 = v.x - __uint_as_float(H0 << 16);
        float r1 = v.y - __uint_as_float(H0 & 0xffff0000u);
        float r2 = v.z - __uint_as_float(H1 << 16);
        float r3 = v.w - __uint_as_float(H1 & 0xffff0000u);
        *(uint2*)(Xh + m*SPITCH + k4) = make_uint2(H0, H1);
        *(uint2*)(Xl + m*SPITCH + k4) = make_uint2(packbf(r0, r1), packbf(r2, r3));
        float4 w = *(const float4*)(Wg + (size_t)m*128 + k4);
        uint32_t G0 = packbf(w.x, w.y), G1 = packbf(w.z, w.w);
        float s0 = w.x - __uint_as_float(G0 << 16);
        float s1 = w.y - __uint_as_float(G0 & 0xffff0000u);
        float s2 = w.z - __uint_as_float(G1 << 16);
        float s3 = w.w - __uint_as_float(G1 & 0xffff0000u);
        *(uint2*)(Wh + m*SPITCH + k4) = make_uint2(G0, G1);
        *(uint2*)(Wl + m*SPITCH + k4) = make_uint2(packbf(s0, s1), packbf(s2, s3));
    }
    __syncthreads();

    int w = tid >> 5, l = tid & 31;
    int g = l >> 2, c2 = (l & 3)*2;
    int m0w = w*16;
    #pragma unroll
    for (int j = 0; j < 16; ++j) { acc[j][0]=0.f; acc[j][1]=0.f; acc[j][2]=0.f; acc[j][3]=0.f; }

    #pragma unroll
    for (int ks = 0; ks < 8; ++ks) {
        int kb = ks*16;
        uint32_t ah0 = *(const uint32_t*)(Xh + (m0w+g)*SPITCH + kb + c2);
        uint32_t ah1 = *(const uint32_t*)(Xh + (m0w+g+8)*SPITCH + kb + c2);
        uint32_t ah2 = *(const uint32_t*)(Xh + (m0w+g)*SPITCH + kb + c2 + 8);
        uint32_t ah3 = *(const uint32_t*)(Xh + (m0w+g+8)*SPITCH + kb + c2 + 8);
        uint32_t al0 = *(const uint32_t*)(Xl + (m0w+g)*SPITCH + kb + c2);
        uint32_t al1 = *(const uint32_t*)(Xl + (m0w+g+8)*SPITCH + kb + c2);
        uint32_t al2 = *(const uint32_t*)(Xl + (m0w+g)*SPITCH + kb + c2 + 8);
        uint32_t al3 = *(const uint32_t*)(Xl + (m0w+g+8)*SPITCH + kb + c2 + 8);
        #pragma unroll
        for (int j = 0; j < 16; ++j) {
            int n0 = 8*j;
            uint32_t bh0 = *(const uint32_t*)(Wh + (n0+g)*SPITCH + kb + c2);
            uint32_t bh1 = *(const uint32_t*)(Wh + (n0+g)*SPITCH + kb + c2 + 8);
            uint32_t bl0 = *(const uint32_t*)(Wl + (n0+g)*SPITCH + kb + c2);
            uint32_t bl1 = *(const uint32_t*)(Wl + (n0+g)*SPITCH + kb + c2 + 8);
            mma16816(acc[j], ah0,ah1,ah2,ah3, bh0,bh1);
            mma16816(acc[j], ah0,ah1,ah2,ah3, bl0,bl1);
            mma16816(acc[j], al0,al1,al2,al3, bh0,bh1);
        }
    }
    __syncthreads();   // done reading tiles; smem reusable for staging
}

// ============================================================
// QKV projection (tensorized) + staged coalesced bf16 hi/lo stores
// ============================================================
__global__ void __launch_bounds__(256) proj_qkv_kernel(
    const float* __restrict__ x,
    const float* __restrict__ Wq, const float* __restrict__ bq,
    const float* __restrict__ Wk, const float* __restrict__ bk,
    const float* __restrict__ Wv, const float* __restrict__ bv)
{
    extern __shared__ char smc[];
    int sel = blockIdx.y;
    const float* W    = (sel==0)?Wq:(sel==1)?Wk:Wv;
    const float* bias = (sel==0)?bq:(sel==1)?bk:bv;
    float scale = (sel==0)?(0.25f*1.4426950408889634f):1.0f;
    int m0 = blockIdx.x * 128;

    float acc[16][4];
    proj_mma_tile(x, W, bias, smc, m0, acc);

    float* bias_s = (float*)(smc + P_BIAS);
    __nv_bfloat16* Sh = (__nv_bfloat16*)smc;
    __nv_bfloat16* Sl = Sh + 16384;
    int tid = threadIdx.x, w = tid >> 5, l = tid & 31;
    int g = l >> 2, c2 = (l & 3)*2;
    int r0 = w*16 + g, r1 = r0 + 8;

    #pragma unroll
    for (int j = 0; j < 16; ++j) {
        int n0 = 8*j;
        #pragma unroll
        for (int e = 0; e < 4; ++e) {
            int col = n0 + c2 + (e & 1);
            int r = (e < 2) ? r0 : r1;
            float v = (acc[j][e] + bias_s[col]) * scale;
            __nv_bfloat16 hb = __float2bfloat16_rn(v);
            __nv_bfloat16 lb = __float2bfloat16_rn(v - __bfloat162float(hb));
            int head = col >> 4, hd = col & 15;
            int off = (sel < 2) ? (head*2048 + r*16 + hd)
                                : (head*2048 + hd*128 + r);
            Sh[off] = hb; Sl[off] = lb;
        }
    }
    __syncthreads();

    int bt = m0 / Nc, nbase = m0 % Nc;
    __nv_bfloat16* GH = (sel==0)?g_qh:(sel==1)?g_kh:g_vth;
    __nv_bfloat16* GL = (sel==0)?g_ql:(sel==1)?g_kl:g_vtl;
    const uint4* sh4 = (const uint4*)Sh;
    const uint4* sl4 = (const uint4*)Sl;
    #pragma unroll
    for (int it = 0; it < 8; ++it) {
        int i4 = it*256 + tid;                  // 0..2047
        int head = i4 >> 8, rem = i4 & 255;     // 256 uint4 per head
        if (sel < 2) {
            size_t gbase = (((size_t)(bt*Hc + head))*Nc + nbase)*HDc;
            ((uint4*)(GH + gbase))[rem] = sh4[i4];
            ((uint4*)(GL + gbase))[rem] = sl4[i4];
        } else {
            int hd = rem >> 4, n8 = rem & 15;
            size_t gbase = ((size_t)(bt*Hc + head))*HDc*Nc + (size_t)hd*Nc + nbase;
            ((uint4*)(GH + gbase))[n8] = sh4[i4];
            ((uint4*)(GL + gbase))[n8] = sl4[i4];
        }
    }
}

// ============================================================
// O projection (tensorized): out = ctx @ Wo^T + bo, staged f32 coalesced
// ============================================================
__global__ void __launch_bounds__(256) proj_o_kernel(
    const float* __restrict__ Wo, const float* __restrict__ bo, float* __restrict__ out)
{
    extern __shared__ char smc[];
    int m0 = blockIdx.x * 128;
    float acc[16][4];
    proj_mma_tile(g_ctx, Wo, bo, smc, m0, acc);

    float* bias_s = (float*)(smc + P_BIAS);
    float* Sf = (float*)smc;   // [128][132]
    int tid = threadIdx.x, w = tid >> 5, l = tid & 31;
    int g = l >> 2, c2 = (l & 3)*2;
    int r0 = w*16 + g, r1 = r0 + 8;
    #pragma unroll
    for (int j = 0; j < 16; ++j) {
        int n0 = 8*j;
        Sf[r0*132 + n0 + c2]     = acc[j][0] + bias_s[n0 + c2];
        Sf[r0*132 + n0 + c2 + 1] = acc[j][1] + bias_s[n0 + c2 + 1];
        Sf[r1*132 + n0 + c2]     = acc[j][2] + bias_s[n0 + c2];
        Sf[r1*132 + n0 + c2 + 1] = acc[j][3] + bias_s[n0 + c2 + 1];
    }
    __syncthreads();
    #pragma unroll
    for (int it = 0; it < 16; ++it) {
        int i4 = it*256 + tid;          // 0..4095
        int row = i4 >> 5, c4 = (i4 & 31)*4;
        *(float4*)(out + (size_t)(m0+row)*128 + c4) = *(const float4*)(Sf + row*132 + c4);
    }
}

// ============================================================
// bf16x3 warp-MMA flash attention (UNCHANGED from the 269us version)
// ============================================================
__device__ __forceinline__ void issue_loads(int it, int t, uint32_t sb,
    const __nv_bfloat16* gqh, const __nv_bfloat16* gql,
    const __nv_bfloat16* gkh, const __nv_bfloat16* gkl,
    const __nv_bfloat16* gvh, const __nv_bfloat16* gvl,
    const float* adjg)
{
    int qt = it >> 3, ch = it & 7, b = it & 1;
    int row = t >> 1, hw = t & 1;
    CP16(sb + O_KH + b*6144 + row*48 + hw*16, gkh + (ch*128+row)*16 + hw*8);
    CP16(sb + O_KL + b*6144 + row*48 + hw*16, gkl + (ch*128+row)*16 + hw*8);
    int vg = t >> 4, vp = t & 15;
    CP16(sb + O_VH + b*4352 + vg*272 + vp*16, gvh + vg*1024 + ch*128 + vp*8);
    CP16(sb + O_VL + b*4352 + vg*272 + vp*16, gvl + vg*1024 + ch*128 + vp*8);
    #pragma unroll
    for (int i = 0; i < 16; ++i) {
        int e = i*256 + t, r2 = e >> 5, q4 = e & 31;   // 128 rows x 32 float4
        CP16(sb + O_ADJ + b*67584 + r2*528 + q4*16,
             adjg + (size_t)(qt*128 + r2)*1024 + ch*128 + q4*4);
    }
    if (ch == 0) {
        int qb = qt & 1;
        CP16(sb + O_QH + qb*6144 + row*48 + hw*16, gqh + (qt*128+row)*16 + hw*8);
        CP16(sb + O_QL + qb*6144 + row*48 + hw*16, gql + (qt*128+row)*16 + hw*8);
    }
    CP_COMMIT();
}

__global__ void __launch_bounds__(256,1) attn_mma_kernel(const float* __restrict__ adj)
{
    extern __shared__ char smc[];
    uint32_t sb = smem_u32(smc);
    int t = threadIdx.x, w = t >> 5, l = t & 31;
    int g = l >> 2, c2 = (l & 3)*2;
    int bt = blockIdx.x >> 3, h = blockIdx.x & 7, slab = bt*Hc + h;
    int m0 = w*16;

    const __nv_bfloat16* gqh = g_qh + (size_t)slab*Nc*HDc;
    const __nv_bfloat16* gql = g_ql + (size_t)slab*Nc*HDc;
    const __nv_bfloat16* gkh = g_kh + (size_t)slab*Nc*HDc;
    const __nv_bfloat16* gkl = g_kl + (size_t)slab*Nc*HDc;
    const __nv_bfloat16* gvh = g_vth + (size_t)slab*HDc*Nc;
    const __nv_bfloat16* gvl = g_vtl + (size_t)slab*HDc*Nc;
    const float* adjg = adj + ((size_t)bt << 20);

    uint32_t qh0=0,qh1=0,qh2=0,qh3=0, ql0=0,ql1=0,ql2=0,ql3=0;
    float ctx0[4], ctx1[4], sum0 = 0.f, sum1 = 0.f;

    issue_loads(0, t, sb, gqh, gql, gkh, gkl, gvh, gvl, adjg);

    for (int it = 0; it < 64; ++it) {
        CP_WAIT0();
        __syncthreads();
        if (it < 63) issue_loads(it+1, t, sb, gqh, gql, gkh, gkl, gvh, gvl, adjg);

        int qt = it >> 3, ch = it & 7, b = it & 1;
        const __nv_bfloat16* sKh = (const __nv_bfloat16*)(smc + O_KH + b*6144);
        const __nv_bfloat16* sKl = (const __nv_bfloat16*)(smc + O_KL + b*6144);
        const __nv_bfloat16* sVh = (const __nv_bfloat16*)(smc + O_VH + b*4352);
        const __nv_bfloat16* sVl = (const __nv_bfloat16*)(smc + O_VL + b*4352);
        const float* sAdj = (const float*)(smc + O_ADJ + b*67584);

        if (ch == 0) {
            const __nv_bfloat16* sQh = (const __nv_bfloat16*)(smc + O_QH + (qt&1)*6144);
            const __nv_bfloat16* sQl = (const __nv_bfloat16*)(smc + O_QL + (qt&1)*6144);
            qh0 = *(const uint32_t*)(sQh + (m0+g)*24 + c2);
            qh1 = *(const uint32_t*)(sQh + (m0+g+8)*24 + c2);
            qh2 = *(const uint32_t*)(sQh + (m0+g)*24 + c2 + 8);
            qh3 = *(const uint32_t*)(sQh + (m0+g+8)*24 + c2 + 8);
            ql0 = *(const uint32_t*)(sQl + (m0+g)*24 + c2);
            ql1 = *(const uint32_t*)(sQl + (m0+g+8)*24 + c2);
            ql2 = *(const uint32_t*)(sQl + (m0+g)*24 + c2 + 8);
            ql3 = *(const uint32_t*)(sQl + (m0+g+8)*24 + c2 + 8);
            ctx0[0]=ctx0[1]=ctx0[2]=ctx0[3]=0.f;
            ctx1[0]=ctx1[1]=ctx1[2]=ctx1[3]=0.f;
            sum0 = 0.f; sum1 = 0.f;
        }

        // ---- S = Q K^T (bf16x3) ----
        float sacc[16][4];
        #pragma unroll
        for (int j = 0; j < 16; ++j) { sacc[j][0]=0.f; sacc[j][1]=0.f; sacc[j][2]=0.f; sacc[j][3]=0.f; }
        #pragma unroll
        for (int j = 0; j < 16; ++j) {
            int n0 = 8*j;
            uint32_t bh0 = *(const uint32_t*)(sKh + (n0+g)*24 + c2);
            uint32_t bh1 = *(const uint32_t*)(sKh + (n0+g)*24 + c2 + 8);
            uint32_t bl0 = *(const uint32_t*)(sKl + (n0+g)*24 + c2);
            uint32_t bl1 = *(const uint32_t*)(sKl + (n0+g)*24 + c2 + 8);
            mma16816(sacc[j], qh0,qh1,qh2,qh3, bh0,bh1);
            mma16816(sacc[j], qh0,qh1,qh2,qh3, bl0,bl1);
            mma16816(sacc[j], ql0,ql1,ql2,ql3, bh0,bh1);
        }

        // ---- epilogue: p = ex2(s)*adj, split to bf16 hi/lo A-frags ----
        uint32_t phA[16], phB[16], plA[16], plB[16];
        #pragma unroll
        for (int j = 0; j < 16; ++j) {
            float2 aA = *(const float2*)(sAdj + (m0+g)*132 + 8*j + c2);
            float2 aB = *(const float2*)(sAdj + (m0+g+8)*132 + 8*j + c2);
            float p0 = fast_ex2(sacc[j][0]) * aA.x;
            float p1 = fast_ex2(sacc[j][1]) * aA.y;
            float p2 = fast_ex2(sacc[j][2]) * aB.x;
            float p3 = fast_ex2(sacc[j][3]) * aB.y;
            sum0 += p0 + p1; sum1 += p2 + p3;
            uint32_t hA = packbf(p0, p1), hB = packbf(p2, p3);
            phA[j] = hA; phB[j] = hB;
            plA[j] = packbf(p0 - __uint_as_float(hA << 16), p1 - __uint_as_float(hA & 0xffff0000u));
            plB[j] = packbf(p2 - __uint_as_float(hB << 16), p3 - __uint_as_float(hB & 0xffff0000u));
        }

        // ---- ctx += P V (bf16x3) ----
        #pragma unroll
        for (int kk = 0; kk < 8; ++kk) {
            int k0 = 16*kk;
            uint32_t vh0 = *(const uint32_t*)(sVh + g*136 + k0 + c2);
            uint32_t vh1 = *(const uint32_t*)(sVh + g*136 + k0 + c2 + 8);
            uint32_t vl0 = *(const uint32_t*)(sVl + g*136 + k0 + c2);
            uint32_t vl1 = *(const uint32_t*)(sVl + g*136 + k0 + c2 + 8);
            uint32_t wh0 = *(const uint32_t*)(sVh + (g+8)*136 + k0 + c2);
            uint32_t wh1 = *(const uint32_t*)(sVh + (g+8)*136 + k0 + c2 + 8);
            uint32_t wl0 = *(const uint32_t*)(sVl + (g+8)*136 + k0 + c2);
            uint32_t wl1 = *(const uint32_t*)(sVl + (g+8)*136 + k0 + c2 + 8);
            uint32_t a0 = phA[2*kk], a1 = phB[2*kk], a2 = phA[2*kk+1], a3 = phB[2*kk+1];
            uint32_t e0 = plA[2*kk], e1 = plB[2*kk], e2 = plA[2*kk+1], e3 = plB[2*kk+1];
            mma16816(ctx0, a0,a1,a2,a3, vh0,vh1);
            mma16816(ctx0, a0,a1,a2,a3, vl0,vl1);
            mma16816(ctx0, e0,e1,e2,e3, vh0,vh1);
            mma16816(ctx1, a0,a1,a2,a3, wh0,wh1);
            mma16816(ctx1, a0,a1,a2,a3, wl0,wl1);
            mma16816(ctx1, e0,e1,e2,e3, wh0,wh1);
        }

        if (ch == 7) {
            float s0 = sum0, s1 = sum1;
            s0 += __shfl_xor_sync(0xffffffffu, s0, 1);
            s0 += __shfl_xor_sync(0xffffffffu, s0, 2);
            s1 += __shfl_xor_sync(0xffffffffu, s1, 1);
            s1 += __shfl_xor_sync(0xffffffffu, s1, 2);
            float inv0 = 1.0f / (s0 + 1e-8f), inv1 = 1.0f / (s1 + 1e-8f);
            int qr = qt*128 + m0 + g;
            float* op  = g_ctx + ((size_t)(bt*Nc + qr))*Dc + h*HDc;
            float* op2 = op + 8*Dc;
            float2 o;
            o.x = ctx0[0]*inv0; o.y = ctx0[1]*inv0; *(float2*)(op + c2) = o;
            o.x = ctx1[0]*inv0; o.y = ctx1[1]*inv0; *(float2*)(op + 8 + c2) = o;
            o.x = ctx0[2]*inv1; o.y = ctx0[3]*inv1; *(float2*)(op2 + c2) = o;
            o.x = ctx1[2]*inv1; o.y = ctx1[3]*inv1; *(float2*)(op2 + 8 + c2) = o;
        }
    }
}

// ============================================================
extern "C" void kernel_launch(void* const* d_in, const int* in_sizes, int n_in,
                              void* d_out, int out_size)
{
    const float* x   = (const float*)d_in[0];
    const float* adj = (const float*)d_in[1];
    const float* Wq  = (const float*)d_in[2];
    const float* bq  = (const float*)d_in[3];
    const float* Wk  = (const float*)d_in[4];
    const float* bk  = (const float*)d_in[5];
    const float* Wv  = (const float*)d_in[6];
    const float* bv  = (const float*)d_in[7];
    const float* Wo  = (const float*)d_in[8];
    const float* bo  = (const float*)d_in[9];
    float* out = (float*)d_out;

    cudaFuncSetAttribute(proj_qkv_kernel, cudaFuncAttributeMaxDynamicSharedMemorySize, SMEM_PROJ);
    cudaFuncSetAttribute(proj_o_kernel,   cudaFuncAttributeMaxDynamicSharedMemorySize, SMEM_PROJ);
    cudaFuncSetAttribute(attn_mma_kernel, cudaFuncAttributeMaxDynamicSharedMemorySize, SMEM_ATTN);

    dim3 gqkv(Mc/128, 3);
    proj_qkv_kernel<<<gqkv, 256, SMEM_PROJ>>>(x, Wq, bq, Wk, bk, Wv, bv);
    attn_mma_kernel<<<BTc*Hc, 256, SMEM_ATTN>>>(adj);
    proj_o_kernel<<<Mc/128, 256, SMEM_PROJ>>>(Wo, bo, out);
}